// round 14
// baseline (speedup 1.0000x reference)
#include <cuda_runtime.h>

#define N_NODES 10000
#define N_EDGES 160000
#define TE 32                    // edges per block in the edge kernel

#define INV_SQRT_MUL 0.08838834764831845f   // 1/sqrt(128)
#define INV_SQRT3    0.57735026918962576f
#define OUT_SCALE    0.00390625f            // (1/sqrt(256)) / 16

typedef unsigned long long ull;

// ---------------------------------------------------------------------------
// Scratch (device globals: allocation-free)
// ---------------------------------------------------------------------------
__device__ float g_hps[N_NODES * 128];   // s_in @ (inv * W_scalar @ W1[0:128])
__device__ float g_hpr[N_NODES * 128];   // s_in @ (inv * W_scalar @ W1[128:256])
__device__ float g_su [N_NODES * 128];   // s_up
__device__ float g_vup[N_NODES * 384];   // v_up, layout [n][w][i] (i fastest)
__device__ float g_msg[N_NODES * 1024];  // segment-sum accumulator
__device__ float g_Wsa[128 * 128];       // inv * W_scalar @ W1[0:128]
__device__ float g_Wsb[128 * 128];       // inv * W_scalar @ W1[128:256]

static __device__ __forceinline__ float silu(float x) {
    return x / (1.0f + __expf(-x));
}

static __device__ __forceinline__ void red_add_v4(float* addr, float a, float b,
                                                  float c, float d) {
    asm volatile("red.global.add.v4.f32 [%0], {%1, %2, %3, %4};"
                 :: "l"(addr), "f"(a), "f"(b), "f"(c), "f"(d) : "memory");
}

static __device__ __forceinline__ void prefetch_l1(const void* p) {
    asm volatile("prefetch.global.L1 [%0];" :: "l"(p));
}

// ---- packed f32x2 helpers --------------------------------------------------
static __device__ __forceinline__ ull dup2(float x) {
    ull r; asm("mov.b64 %0, {%1, %1};" : "=l"(r) : "f"(x)); return r;
}
static __device__ __forceinline__ void fma2(ull& acc, ull a, ull b) {
    asm("fma.rn.f32x2 %0, %1, %2, %0;" : "+l"(acc) : "l"(a), "l"(b));
}
static __device__ __forceinline__ float2 unpack2(ull p) {
    float2 f; asm("mov.b64 {%0, %1}, %2;" : "=f"(f.x), "=f"(f.y) : "l"(p)); return f;
}

// ---------------------------------------------------------------------------
// Kernel 0: zero the message accumulator
// ---------------------------------------------------------------------------
__global__ void k_zero() {
    int i = blockIdx.x * blockDim.x + threadIdx.x;
    ((float4*)g_msg)[i] = make_float4(0.f, 0.f, 0.f, 0.f);
}

// ---------------------------------------------------------------------------
// Kernel W: fold W_scalar into the first MLP layer.
// ---------------------------------------------------------------------------
__global__ void __launch_bounds__(128) k_w(
    const float* __restrict__ Ws, const float* __restrict__ W1)
{
    __shared__ float row[128];
    const int u = blockIdx.x, t = threadIdx.x;
    row[t] = Ws[u * 128 + t];
    __syncthreads();
    const float* W1p = W1 + (blockIdx.y ? 128 * 128 : 0);
    float a = 0.f;
#pragma unroll 4
    for (int c = 0; c < 128; ++c) a += row[c] * W1p[c * 128 + t];
    (blockIdx.y ? g_Wsb : g_Wsa)[u * 128 + t] = a * INV_SQRT_MUL;
}

// ---------------------------------------------------------------------------
// Kernel 1: per-node precompute, 4 nodes per block (round-9 version).
// ---------------------------------------------------------------------------
__global__ void __launch_bounds__(128) k_node(
    const float* __restrict__ nf,
    const float* __restrict__ Wu0,
    const float* __restrict__ Wu1)
{
    __shared__ float s_sh[4][128];
    __shared__ float v_sh[4][384];
    const int n0 = blockIdx.x * 4;
    const int t = threadIdx.x;

#pragma unroll
    for (int nn = 0; nn < 4; ++nn) {
        const float* src = nf + (n0 + nn) * 512;
        s_sh[nn][t]       = src[t];
        v_sh[nn][t]       = src[128 + t];
        v_sh[nn][t + 128] = src[256 + t];
        v_sh[nn][t + 256] = src[384 + t];
    }
    __syncthreads();

    float as[4], ar[4], a1[4], av0[4], av1[4], av2[4];
#pragma unroll
    for (int nn = 0; nn < 4; ++nn) {
        as[nn]=0.f; ar[nn]=0.f; a1[nn]=0.f; av0[nn]=0.f; av1[nn]=0.f; av2[nn]=0.f;
    }

#pragma unroll 2
    for (int u = 0; u < 128; ++u) {
        float wsa = g_Wsa[u * 128 + t];
        float wsb = g_Wsb[u * 128 + t];
        float wu0 = Wu0[u * 128 + t];
        float wu1 = Wu1[u * 128 + t];
#pragma unroll
        for (int nn = 0; nn < 4; ++nn) {
            float s = s_sh[nn][u];
            as[nn] += s * wsa;
            ar[nn] += s * wsb;
            a1[nn] += s * wu0;
            av0[nn] += v_sh[nn][u * 3 + 0] * wu1;
            av1[nn] += v_sh[nn][u * 3 + 1] * wu1;
            av2[nn] += v_sh[nn][u * 3 + 2] * wu1;
        }
    }
#pragma unroll
    for (int nn = 0; nn < 4; ++nn) {
        int n = n0 + nn;
        g_hps[n * 128 + t] = as[nn];
        g_hpr[n * 128 + t] = ar[nn];
        g_su [n * 128 + t] = a1[nn] * INV_SQRT_MUL;
        g_vup[n * 384 + t * 3 + 0] = av0[nn] * INV_SQRT_MUL;
        g_vup[n * 384 + t * 3 + 1] = av1[nn] * INV_SQRT_MUL;
        g_vup[n * 384 + t * 3 + 2] = av2[nn] * INV_SQRT_MUL;
    }
}

// ---------------------------------------------------------------------------
// Kernel 2: per-edge MLP + message + scatter, f32x2 edge-pair packing.
// Round-9 structure + prefetch.global.L1 of weight rows 8 k-iterations
// ahead (clamped) so the W3 stream is L1-resident by demand time.
// ---------------------------------------------------------------------------
__global__ void __launch_bounds__(128, 8) k_edge(
    const float* __restrict__ edge_attrs,
    const float* __restrict__ edge_feats,
    const float* __restrict__ lengths,
    const int*   __restrict__ edge_index,
    const float* __restrict__ W1, const float* __restrict__ b1,
    const float* __restrict__ W2, const float* __restrict__ b2,
    const float* __restrict__ W3)
{
    __shared__ __align__(16) float2 hT[128][18];   // [col k][edge pair], 144B rows
    __shared__ int s_idx[2][TE];                   // [0]=snd, [1]=rcv

    const int t  = threadIdx.x;
    const int cg = t & 31;
    const int c0 = cg * 4;
    const int wp = t >> 5;
    const int e0 = wp * 8;
    const int p0 = wp * 4;
    const int ebase = blockIdx.x * TE;

    if (t < 64) {
        const int e = t & 31;
        const int r = t >> 5;
        s_idx[r][e] = edge_index[r * N_EDGES + ebase + e];
    }
    __syncthreads();

    // ---- layer 1 (folded): per pair, compute both edges' 4 cols ----
    {
        float4 bb = *(const float4*)(b1 + c0);
#pragma unroll
        for (int jp = 0; jp < 4; ++jp) {
            float a2[2][4];
#pragma unroll
            for (int h = 0; h < 2; ++h) {
                const int el  = e0 + 2 * jp + h;
                const int eg  = ebase + el;
                const int snd = s_idx[0][el];
                const int rcv = s_idx[1][el];
                float4 hs = *(const float4*)(g_hps + snd * 128 + c0);
                float4 hr = *(const float4*)(g_hpr + rcv * 128 + c0);
                float a[4] = { bb.x + hs.x + hr.x, bb.y + hs.y + hr.y,
                               bb.z + hs.z + hr.z, bb.w + hs.w + hr.w };
                float ef[9];
                {
                    float4 q0 = *(const float4*)(edge_feats + eg * 8);
                    float4 q1 = *(const float4*)(edge_feats + eg * 8 + 4);
                    ef[0]=q0.x; ef[1]=q0.y; ef[2]=q0.z; ef[3]=q0.w;
                    ef[4]=q1.x; ef[5]=q1.y; ef[6]=q1.z; ef[7]=q1.w;
                    ef[8]=lengths[eg];
                }
#pragma unroll
                for (int r = 0; r < 9; ++r) {
                    float4 w = *(const float4*)(W1 + (256 + r) * 128 + c0);
                    a[0] += ef[r] * w.x; a[1] += ef[r] * w.y;
                    a[2] += ef[r] * w.z; a[3] += ef[r] * w.w;
                }
                a2[h][0]=silu(a[0]); a2[h][1]=silu(a[1]);
                a2[h][2]=silu(a[2]); a2[h][3]=silu(a[3]);
            }
#pragma unroll
            for (int i = 0; i < 4; ++i)
                hT[c0 + i][p0 + jp] = make_float2(a2[0][i], a2[1][i]);
        }
    }
    __syncthreads();

    // ---- layer 2: 128 -> 128, silu; acc[col][pair] ----
    {
        ull acc[4][4];
        {
            float4 b = *(const float4*)(b2 + c0);
            ull b0 = dup2(b.x), b1d = dup2(b.y), b2d = dup2(b.z), b3 = dup2(b.w);
#pragma unroll
            for (int jp = 0; jp < 4; ++jp) {
                acc[0][jp] = b0; acc[1][jp] = b1d; acc[2][jp] = b2d; acc[3][jp] = b3;
            }
        }
#pragma unroll 2
        for (int k = 0; k < 128; ++k) {
            int kp = k + 8 > 127 ? 127 : k + 8;
            prefetch_l1(W2 + kp * 128 + c0);
            float4 w = *(const float4*)(W2 + k * 128 + c0);
            ull wd0 = dup2(w.x), wd1 = dup2(w.y), wd2 = dup2(w.z), wd3 = dup2(w.w);
            ulonglong2 xa = *(const ulonglong2*)&hT[k][p0];
            ulonglong2 xb = *(const ulonglong2*)&hT[k][p0 + 2];
            fma2(acc[0][0], wd0, xa.x); fma2(acc[0][1], wd0, xa.y);
            fma2(acc[0][2], wd0, xb.x); fma2(acc[0][3], wd0, xb.y);
            fma2(acc[1][0], wd1, xa.x); fma2(acc[1][1], wd1, xa.y);
            fma2(acc[1][2], wd1, xb.x); fma2(acc[1][3], wd1, xb.y);
            fma2(acc[2][0], wd2, xa.x); fma2(acc[2][1], wd2, xa.y);
            fma2(acc[2][2], wd2, xb.x); fma2(acc[2][3], wd2, xb.y);
            fma2(acc[3][0], wd3, xa.x); fma2(acc[3][1], wd3, xa.y);
            fma2(acc[3][2], wd3, xb.x); fma2(acc[3][3], wd3, xb.y);
        }
        __syncthreads();             // all h1 reads complete
#pragma unroll
        for (int i = 0; i < 4; ++i)
#pragma unroll
            for (int jp = 0; jp < 4; ++jp) {
                float2 v = unpack2(acc[i][jp]);
                hT[c0 + i][p0 + jp] = make_float2(silu(v.x), silu(v.y));
            }
    }
    __syncthreads();
    // h2 now lives in hT, read-only below.

    // ======== layer 3: four single-segment sweeps, fused scatter ==========
#pragma unroll 1
    for (int seg = 0; seg < 4; ++seg) {
        ull acc[4][4];
#pragma unroll
        for (int i = 0; i < 4; ++i)
#pragma unroll
            for (int jp = 0; jp < 4; ++jp) acc[i][jp] = 0;

        const float* Wseg = W3 + seg * 128 + c0;
#pragma unroll 2
        for (int k = 0; k < 128; ++k) {
            int kp = k + 8 > 127 ? 127 : k + 8;
            prefetch_l1(Wseg + kp * 512);
            float4 w = *(const float4*)(Wseg + k * 512);
            ull wd0 = dup2(w.x), wd1 = dup2(w.y), wd2 = dup2(w.z), wd3 = dup2(w.w);
            ulonglong2 xa = *(const ulonglong2*)&hT[k][p0];
            ulonglong2 xb = *(const ulonglong2*)&hT[k][p0 + 2];
            fma2(acc[0][0], wd0, xa.x); fma2(acc[0][1], wd0, xa.y);
            fma2(acc[0][2], wd0, xb.x); fma2(acc[0][3], wd0, xb.y);
            fma2(acc[1][0], wd1, xa.x); fma2(acc[1][1], wd1, xa.y);
            fma2(acc[1][2], wd1, xb.x); fma2(acc[1][3], wd1, xb.y);
            fma2(acc[2][0], wd2, xa.x); fma2(acc[2][1], wd2, xa.y);
            fma2(acc[2][2], wd2, xb.x); fma2(acc[2][3], wd2, xb.y);
            fma2(acc[3][0], wd3, xa.x); fma2(acc[3][1], wd3, xa.y);
            fma2(acc[3][2], wd3, xb.x); fma2(acc[3][3], wd3, xb.y);
        }

        // ---- fused scatter for this segment ----
#pragma unroll
        for (int jp = 0; jp < 4; ++jp) {
            float2 vc0 = unpack2(acc[0][jp]);
            float2 vc1 = unpack2(acc[1][jp]);
            float2 vc2 = unpack2(acc[2][jp]);
            float2 vc3 = unpack2(acc[3][jp]);
#pragma unroll
            for (int h = 0; h < 2; ++h) {
                const int el  = e0 + 2 * jp + h;
                const int eg  = ebase + el;
                const int snd = s_idx[0][el];
                const int rcv = s_idx[1][el];
                float4 ea = *(const float4*)(edge_attrs + eg * 4);
                const float av[4] = { h ? vc0.y : vc0.x, h ? vc1.y : vc1.x,
                                      h ? vc2.y : vc2.x, h ? vc3.y : vc3.x };
                float* base = g_msg + rcv * 1024;

                if (seg == 0) {          // m0a = w0*se*y0 -> [0,128)
                    float4 sev = *(const float4*)(g_su + snd * 128 + c0);
                    red_add_v4(base + c0,
                               av[0]*sev.x*ea.x, av[1]*sev.y*ea.x,
                               av[2]*sev.z*ea.x, av[3]*sev.w*ea.x);
                } else if (seg == 1) {   // m1a = (w1*se) (x) y1 -> [256,640)
                    float4 sev = *(const float4*)(g_su + snd * 128 + c0);
                    const float se[4] = {sev.x, sev.y, sev.z, sev.w};
                    float o[12];
#pragma unroll
                    for (int m = 0; m < 4; ++m) {
                        float t1 = av[m] * se[m];
                        o[3*m+0] = t1 * ea.y; o[3*m+1] = t1 * ea.z; o[3*m+2] = t1 * ea.w;
                    }
                    float* p = base + 256 + c0 * 3;
                    red_add_v4(p,     o[0], o[1], o[2],  o[3]);
                    red_add_v4(p + 4, o[4], o[5], o[6],  o[7]);
                    red_add_v4(p + 8, o[8], o[9], o[10], o[11]);
                } else if (seg == 2) {   // m1b = (w2*y0) * ve -> [640,1024)
                    const float4* pv = (const float4*)(g_vup + snd * 384 + c0 * 3);
                    float4 v0 = pv[0], v1 = pv[1], v2 = pv[2];
                    float o[12];
                    o[0]  = av[0]*ea.x*v0.x; o[1]  = av[0]*ea.x*v0.y; o[2]  = av[0]*ea.x*v0.z;
                    o[3]  = av[1]*ea.x*v0.w; o[4]  = av[1]*ea.x*v1.x; o[5]  = av[1]*ea.x*v1.y;
                    o[6]  = av[2]*ea.x*v1.z; o[7]  = av[2]*ea.x*v1.w; o[8]  = av[2]*ea.x*v2.x;
                    o[9]  = av[3]*ea.x*v2.y; o[10] = av[3]*ea.x*v2.z; o[11] = av[3]*ea.x*v2.w;
                    float* p = base + 640 + c0 * 3;
                    red_add_v4(p,     o[0], o[1], o[2],  o[3]);
                    red_add_v4(p + 4, o[4], o[5], o[6],  o[7]);
                    red_add_v4(p + 8, o[8], o[9], o[10], o[11]);
                } else {                 // m0b = w3*(ve.y1)*inv_sqrt3 -> [128,256)
                    const float4* pv = (const float4*)(g_vup + snd * 384 + c0 * 3);
                    float4 v0 = pv[0], v1 = pv[1], v2 = pv[2];
                    float d0 = v0.x*ea.y + v0.y*ea.z + v0.z*ea.w;
                    float d1 = v0.w*ea.y + v1.x*ea.z + v1.y*ea.w;
                    float d2 = v1.z*ea.y + v1.w*ea.z + v2.x*ea.w;
                    float d3 = v2.y*ea.y + v2.z*ea.z + v2.w*ea.w;
                    red_add_v4(base + 128 + c0,
                               av[0]*d0*INV_SQRT3, av[1]*d1*INV_SQRT3,
                               av[2]*d2*INV_SQRT3, av[3]*d3*INV_SQRT3);
                }
            }
        }
    }
}

// ---------------------------------------------------------------------------
// Kernel 3: node output. 8 nodes per block, 256 threads.
// ---------------------------------------------------------------------------
__global__ void __launch_bounds__(256) k_out(
    const float* __restrict__ W0,
    const float* __restrict__ W1o,
    float* __restrict__ out)
{
    __shared__ __align__(16) float m_sm[8 * 1024];
    const int n0 = blockIdx.x * 8;
    const int t  = threadIdx.x;
    const int tc = t & 127;
    const int nb = (t >> 7) * 4;      // node group base: 0 or 4

    {
        const float4* src = (const float4*)(g_msg + n0 * 1024);
        float4* dst = (float4*)m_sm;
#pragma unroll
        for (int i = 0; i < 8; ++i) dst[t + 256 * i] = src[t + 256 * i];
    }
    __syncthreads();

    float a0[4], v0[4], v1[4], v2[4];
#pragma unroll
    for (int nn = 0; nn < 4; ++nn) { a0[nn]=0.f; v0[nn]=0.f; v1[nn]=0.f; v2[nn]=0.f; }

    for (int u = 0; u < 256; u += 4) {
        float w0[4], w1[4];
#pragma unroll
        for (int i = 0; i < 4; ++i) {
            w0[i] = W0 [(u + i) * 128 + tc];
            w1[i] = W1o[(u + i) * 128 + tc];
        }
#pragma unroll
        for (int nn = 0; nn < 4; ++nn) {
            const float* row = m_sm + (nb + nn) * 1024;
            float4 ms = *(const float4*)&row[u];
            a0[nn] += ms.x * w0[0] + ms.y * w0[1] + ms.z * w0[2] + ms.w * w0[3];
            float4 va = *(const float4*)&row[256 + u * 3];
            float4 vb = *(const float4*)&row[256 + u * 3 + 4];
            float4 vc = *(const float4*)&row[256 + u * 3 + 8];
            v0[nn] += va.x * w1[0] + va.w * w1[1] + vb.z * w1[2] + vc.y * w1[3];
            v1[nn] += va.y * w1[0] + vb.x * w1[1] + vb.w * w1[2] + vc.z * w1[3];
            v2[nn] += va.z * w1[0] + vb.y * w1[1] + vc.x * w1[2] + vc.w * w1[3];
        }
    }

#pragma unroll
    for (int nn = 0; nn < 4; ++nn) {
        *(float4*)(out + (n0 + nb + nn) * 512 + tc * 4) =
            make_float4(a0[nn] * OUT_SCALE, v0[nn] * OUT_SCALE,
                        v1[nn] * OUT_SCALE, v2[nn] * OUT_SCALE);
    }
}

// ---------------------------------------------------------------------------
// Launch
// ---------------------------------------------------------------------------
extern "C" void kernel_launch(void* const* d_in, const int* in_sizes, int n_in,
                              void* d_out, int out_size)
{
    const float* node_feats = (const float*)d_in[0];
    const float* edge_attrs = (const float*)d_in[1];
    const float* edge_feats = (const float*)d_in[2];
    const float* lengths    = (const float*)d_in[3];
    const int*   edge_index = (const int*)  d_in[4];
    const float* W_scalar   = (const float*)d_in[5];
    const float* W_up0      = (const float*)d_in[6];
    const float* W_up1      = (const float*)d_in[7];
    const float* W_mlp1     = (const float*)d_in[8];
    const float* b_mlp1     = (const float*)d_in[9];
    const float* W_mlp2     = (const float*)d_in[10];
    const float* b_mlp2     = (const float*)d_in[11];
    const float* W_mlp3     = (const float*)d_in[12];
    const float* W_out0     = (const float*)d_in[13];
    const float* W_out1     = (const float*)d_in[14];
    float* out = (float*)d_out;

    k_zero<<<5000, 512>>>();
    k_w<<<dim3(128, 2), 128>>>(W_scalar, W_mlp1);
    k_node<<<N_NODES / 4, 128>>>(node_feats, W_up0, W_up1);
    k_edge<<<N_EDGES / TE, 128>>>(edge_attrs, edge_feats, lengths, edge_index,
                                  W_mlp1, b_mlp1, W_mlp2, b_mlp2, W_mlp3);
    k_out<<<N_NODES / 8, 256>>>(W_out0, W_out1, out);
}

// round 15
// speedup vs baseline: 1.1686x; 1.1686x over previous
#include <cuda_runtime.h>

#define N_NODES 10000
#define N_EDGES 160000
#define TE 32                    // edges per block in the edge kernel

#define INV_SQRT_MUL 0.08838834764831845f   // 1/sqrt(128)
#define INV_SQRT3    0.57735026918962576f
#define OUT_SCALE    0.00390625f            // (1/sqrt(256)) / 16

typedef unsigned long long ull;

// ---------------------------------------------------------------------------
// Scratch (device globals: allocation-free)
// ---------------------------------------------------------------------------
__device__ float g_hps[N_NODES * 128];   // s_in @ (inv * W_scalar @ W1[0:128])
__device__ float g_hpr[N_NODES * 128];   // s_in @ (inv * W_scalar @ W1[128:256])
__device__ float g_su [N_NODES * 128];   // s_up
__device__ float g_vup[N_NODES * 384];   // v_up, layout [n][w][i] (i fastest)
__device__ float g_msg[N_NODES * 1024];  // segment-sum accumulator
__device__ float g_Wsa[128 * 128];       // inv * W_scalar @ W1[0:128]
__device__ float g_Wsb[128 * 128];       // inv * W_scalar @ W1[128:256]

static __device__ __forceinline__ float silu(float x) {
    return x / (1.0f + __expf(-x));
}

static __device__ __forceinline__ void red_add_v4(float* addr, float a, float b,
                                                  float c, float d) {
    asm volatile("red.global.add.v4.f32 [%0], {%1, %2, %3, %4};"
                 :: "l"(addr), "f"(a), "f"(b), "f"(c), "f"(d) : "memory");
}

// ---- packed f32x2 helpers --------------------------------------------------
static __device__ __forceinline__ ull dup2(float x) {
    ull r; asm("mov.b64 %0, {%1, %1};" : "=l"(r) : "f"(x)); return r;
}
static __device__ __forceinline__ void fma2(ull& acc, ull a, ull b) {
    asm("fma.rn.f32x2 %0, %1, %2, %0;" : "+l"(acc) : "l"(a), "l"(b));
}
static __device__ __forceinline__ float2 unpack2(ull p) {
    float2 f; asm("mov.b64 {%0, %1}, %2;" : "=f"(f.x), "=f"(f.y) : "l"(p)); return f;
}

// ---------------------------------------------------------------------------
// Kernel W: fold W_scalar into the first MLP layer.
// ---------------------------------------------------------------------------
__global__ void __launch_bounds__(128) k_w(
    const float* __restrict__ Ws, const float* __restrict__ W1)
{
    __shared__ float row[128];
    const int u = blockIdx.x, t = threadIdx.x;
    row[t] = Ws[u * 128 + t];
    __syncthreads();
    const float* W1p = W1 + (blockIdx.y ? 128 * 128 : 0);
    float a = 0.f;
#pragma unroll 4
    for (int c = 0; c < 128; ++c) a += row[c] * W1p[c * 128 + t];
    (blockIdx.y ? g_Wsb : g_Wsa)[u * 128 + t] = a * INV_SQRT_MUL;
}

// ---------------------------------------------------------------------------
// Kernel 1: per-node precompute, 4 nodes per block (round-9 version).
// ---------------------------------------------------------------------------
__global__ void __launch_bounds__(128) k_node(
    const float* __restrict__ nf,
    const float* __restrict__ Wu0,
    const float* __restrict__ Wu1)
{
    __shared__ float s_sh[4][128];
    __shared__ float v_sh[4][384];
    const int n0 = blockIdx.x * 4;
    const int t = threadIdx.x;

#pragma unroll
    for (int nn = 0; nn < 4; ++nn) {
        const float* src = nf + (n0 + nn) * 512;
        s_sh[nn][t]       = src[t];
        v_sh[nn][t]       = src[128 + t];
        v_sh[nn][t + 128] = src[256 + t];
        v_sh[nn][t + 256] = src[384 + t];
    }
    __syncthreads();

    float as[4], ar[4], a1[4], av0[4], av1[4], av2[4];
#pragma unroll
    for (int nn = 0; nn < 4; ++nn) {
        as[nn]=0.f; ar[nn]=0.f; a1[nn]=0.f; av0[nn]=0.f; av1[nn]=0.f; av2[nn]=0.f;
    }

#pragma unroll 2
    for (int u = 0; u < 128; ++u) {
        float wsa = g_Wsa[u * 128 + t];
        float wsb = g_Wsb[u * 128 + t];
        float wu0 = Wu0[u * 128 + t];
        float wu1 = Wu1[u * 128 + t];
#pragma unroll
        for (int nn = 0; nn < 4; ++nn) {
            float s = s_sh[nn][u];
            as[nn] += s * wsa;
            ar[nn] += s * wsb;
            a1[nn] += s * wu0;
            av0[nn] += v_sh[nn][u * 3 + 0] * wu1;
            av1[nn] += v_sh[nn][u * 3 + 1] * wu1;
            av2[nn] += v_sh[nn][u * 3 + 2] * wu1;
        }
    }
#pragma unroll
    for (int nn = 0; nn < 4; ++nn) {
        int n = n0 + nn;
        g_hps[n * 128 + t] = as[nn];
        g_hpr[n * 128 + t] = ar[nn];
        g_su [n * 128 + t] = a1[nn] * INV_SQRT_MUL;
        g_vup[n * 384 + t * 3 + 0] = av0[nn] * INV_SQRT_MUL;
        g_vup[n * 384 + t * 3 + 1] = av1[nn] * INV_SQRT_MUL;
        g_vup[n * 384 + t * 3 + 2] = av2[nn] * INV_SQRT_MUL;
    }
}

// ---------------------------------------------------------------------------
// Kernel 2: per-edge MLP + message + scatter, f32x2 edge-pair packing.
// (Round-9 version, verbatim: proven 797-803us. No prefetch.)
// ---------------------------------------------------------------------------
__global__ void __launch_bounds__(128, 8) k_edge(
    const float* __restrict__ edge_attrs,
    const float* __restrict__ edge_feats,
    const float* __restrict__ lengths,
    const int*   __restrict__ edge_index,
    const float* __restrict__ W1, const float* __restrict__ b1,
    const float* __restrict__ W2, const float* __restrict__ b2,
    const float* __restrict__ W3)
{
    __shared__ __align__(16) float2 hT[128][18];   // [col k][edge pair], 144B rows
    __shared__ int s_idx[2][TE];                   // [0]=snd, [1]=rcv

    const int t  = threadIdx.x;
    const int cg = t & 31;
    const int c0 = cg * 4;
    const int wp = t >> 5;
    const int e0 = wp * 8;
    const int p0 = wp * 4;
    const int ebase = blockIdx.x * TE;

    if (t < 64) {
        const int e = t & 31;
        const int r = t >> 5;
        s_idx[r][e] = edge_index[r * N_EDGES + ebase + e];
    }
    __syncthreads();

    // ---- layer 1 (folded): per pair, compute both edges' 4 cols ----
    {
        float4 bb = *(const float4*)(b1 + c0);
#pragma unroll
        for (int jp = 0; jp < 4; ++jp) {
            float a2[2][4];
#pragma unroll
            for (int h = 0; h < 2; ++h) {
                const int el  = e0 + 2 * jp + h;
                const int eg  = ebase + el;
                const int snd = s_idx[0][el];
                const int rcv = s_idx[1][el];
                float4 hs = *(const float4*)(g_hps + snd * 128 + c0);
                float4 hr = *(const float4*)(g_hpr + rcv * 128 + c0);
                float a[4] = { bb.x + hs.x + hr.x, bb.y + hs.y + hr.y,
                               bb.z + hs.z + hr.z, bb.w + hs.w + hr.w };
                float ef[9];
                {
                    float4 q0 = *(const float4*)(edge_feats + eg * 8);
                    float4 q1 = *(const float4*)(edge_feats + eg * 8 + 4);
                    ef[0]=q0.x; ef[1]=q0.y; ef[2]=q0.z; ef[3]=q0.w;
                    ef[4]=q1.x; ef[5]=q1.y; ef[6]=q1.z; ef[7]=q1.w;
                    ef[8]=lengths[eg];
                }
#pragma unroll
                for (int r = 0; r < 9; ++r) {
                    float4 w = *(const float4*)(W1 + (256 + r) * 128 + c0);
                    a[0] += ef[r] * w.x; a[1] += ef[r] * w.y;
                    a[2] += ef[r] * w.z; a[3] += ef[r] * w.w;
                }
                a2[h][0]=silu(a[0]); a2[h][1]=silu(a[1]);
                a2[h][2]=silu(a[2]); a2[h][3]=silu(a[3]);
            }
#pragma unroll
            for (int i = 0; i < 4; ++i)
                hT[c0 + i][p0 + jp] = make_float2(a2[0][i], a2[1][i]);
        }
    }
    __syncthreads();

    // ---- layer 2: 128 -> 128, silu; acc[col][pair] ----
    {
        ull acc[4][4];
        {
            float4 b = *(const float4*)(b2 + c0);
            ull b0 = dup2(b.x), b1d = dup2(b.y), b2d = dup2(b.z), b3 = dup2(b.w);
#pragma unroll
            for (int jp = 0; jp < 4; ++jp) {
                acc[0][jp] = b0; acc[1][jp] = b1d; acc[2][jp] = b2d; acc[3][jp] = b3;
            }
        }
#pragma unroll 2
        for (int k = 0; k < 128; ++k) {
            float4 w = *(const float4*)(W2 + k * 128 + c0);
            ull wd0 = dup2(w.x), wd1 = dup2(w.y), wd2 = dup2(w.z), wd3 = dup2(w.w);
            ulonglong2 xa = *(const ulonglong2*)&hT[k][p0];
            ulonglong2 xb = *(const ulonglong2*)&hT[k][p0 + 2];
            fma2(acc[0][0], wd0, xa.x); fma2(acc[0][1], wd0, xa.y);
            fma2(acc[0][2], wd0, xb.x); fma2(acc[0][3], wd0, xb.y);
            fma2(acc[1][0], wd1, xa.x); fma2(acc[1][1], wd1, xa.y);
            fma2(acc[1][2], wd1, xb.x); fma2(acc[1][3], wd1, xb.y);
            fma2(acc[2][0], wd2, xa.x); fma2(acc[2][1], wd2, xa.y);
            fma2(acc[2][2], wd2, xb.x); fma2(acc[2][3], wd2, xb.y);
            fma2(acc[3][0], wd3, xa.x); fma2(acc[3][1], wd3, xa.y);
            fma2(acc[3][2], wd3, xb.x); fma2(acc[3][3], wd3, xb.y);
        }
        __syncthreads();             // all h1 reads complete
#pragma unroll
        for (int i = 0; i < 4; ++i)
#pragma unroll
            for (int jp = 0; jp < 4; ++jp) {
                float2 v = unpack2(acc[i][jp]);
                hT[c0 + i][p0 + jp] = make_float2(silu(v.x), silu(v.y));
            }
    }
    __syncthreads();
    // h2 now lives in hT, read-only below.

    // ======== layer 3: four single-segment sweeps, fused scatter ==========
#pragma unroll 1
    for (int seg = 0; seg < 4; ++seg) {
        ull acc[4][4];
#pragma unroll
        for (int i = 0; i < 4; ++i)
#pragma unroll
            for (int jp = 0; jp < 4; ++jp) acc[i][jp] = 0;

        const float* Wseg = W3 + seg * 128 + c0;
#pragma unroll 2
        for (int k = 0; k < 128; ++k) {
            float4 w = *(const float4*)(Wseg + k * 512);
            ull wd0 = dup2(w.x), wd1 = dup2(w.y), wd2 = dup2(w.z), wd3 = dup2(w.w);
            ulonglong2 xa = *(const ulonglong2*)&hT[k][p0];
            ulonglong2 xb = *(const ulonglong2*)&hT[k][p0 + 2];
            fma2(acc[0][0], wd0, xa.x); fma2(acc[0][1], wd0, xa.y);
            fma2(acc[0][2], wd0, xb.x); fma2(acc[0][3], wd0, xb.y);
            fma2(acc[1][0], wd1, xa.x); fma2(acc[1][1], wd1, xa.y);
            fma2(acc[1][2], wd1, xb.x); fma2(acc[1][3], wd1, xb.y);
            fma2(acc[2][0], wd2, xa.x); fma2(acc[2][1], wd2, xa.y);
            fma2(acc[2][2], wd2, xb.x); fma2(acc[2][3], wd2, xb.y);
            fma2(acc[3][0], wd3, xa.x); fma2(acc[3][1], wd3, xa.y);
            fma2(acc[3][2], wd3, xb.x); fma2(acc[3][3], wd3, xb.y);
        }

        // ---- fused scatter for this segment ----
#pragma unroll
        for (int jp = 0; jp < 4; ++jp) {
            float2 vc0 = unpack2(acc[0][jp]);
            float2 vc1 = unpack2(acc[1][jp]);
            float2 vc2 = unpack2(acc[2][jp]);
            float2 vc3 = unpack2(acc[3][jp]);
#pragma unroll
            for (int h = 0; h < 2; ++h) {
                const int el  = e0 + 2 * jp + h;
                const int eg  = ebase + el;
                const int snd = s_idx[0][el];
                const int rcv = s_idx[1][el];
                float4 ea = *(const float4*)(edge_attrs + eg * 4);
                const float av[4] = { h ? vc0.y : vc0.x, h ? vc1.y : vc1.x,
                                      h ? vc2.y : vc2.x, h ? vc3.y : vc3.x };
                float* base = g_msg + rcv * 1024;

                if (seg == 0) {          // m0a = w0*se*y0 -> [0,128)
                    float4 sev = *(const float4*)(g_su + snd * 128 + c0);
                    red_add_v4(base + c0,
                               av[0]*sev.x*ea.x, av[1]*sev.y*ea.x,
                               av[2]*sev.z*ea.x, av[3]*sev.w*ea.x);
                } else if (seg == 1) {   // m1a = (w1*se) (x) y1 -> [256,640)
                    float4 sev = *(const float4*)(g_su + snd * 128 + c0);
                    const float se[4] = {sev.x, sev.y, sev.z, sev.w};
                    float o[12];
#pragma unroll
                    for (int m = 0; m < 4; ++m) {
                        float t1 = av[m] * se[m];
                        o[3*m+0] = t1 * ea.y; o[3*m+1] = t1 * ea.z; o[3*m+2] = t1 * ea.w;
                    }
                    float* p = base + 256 + c0 * 3;
                    red_add_v4(p,     o[0], o[1], o[2],  o[3]);
                    red_add_v4(p + 4, o[4], o[5], o[6],  o[7]);
                    red_add_v4(p + 8, o[8], o[9], o[10], o[11]);
                } else if (seg == 2) {   // m1b = (w2*y0) * ve -> [640,1024)
                    const float4* pv = (const float4*)(g_vup + snd * 384 + c0 * 3);
                    float4 v0 = pv[0], v1 = pv[1], v2 = pv[2];
                    float o[12];
                    o[0]  = av[0]*ea.x*v0.x; o[1]  = av[0]*ea.x*v0.y; o[2]  = av[0]*ea.x*v0.z;
                    o[3]  = av[1]*ea.x*v0.w; o[4]  = av[1]*ea.x*v1.x; o[5]  = av[1]*ea.x*v1.y;
                    o[6]  = av[2]*ea.x*v1.z; o[7]  = av[2]*ea.x*v1.w; o[8]  = av[2]*ea.x*v2.x;
                    o[9]  = av[3]*ea.x*v2.y; o[10] = av[3]*ea.x*v2.z; o[11] = av[3]*ea.x*v2.w;
                    float* p = base + 640 + c0 * 3;
                    red_add_v4(p,     o[0], o[1], o[2],  o[3]);
                    red_add_v4(p + 4, o[4], o[5], o[6],  o[7]);
                    red_add_v4(p + 8, o[8], o[9], o[10], o[11]);
                } else {                 // m0b = w3*(ve.y1)*inv_sqrt3 -> [128,256)
                    const float4* pv = (const float4*)(g_vup + snd * 384 + c0 * 3);
                    float4 v0 = pv[0], v1 = pv[1], v2 = pv[2];
                    float d0 = v0.x*ea.y + v0.y*ea.z + v0.z*ea.w;
                    float d1 = v0.w*ea.y + v1.x*ea.z + v1.y*ea.w;
                    float d2 = v1.z*ea.y + v1.w*ea.z + v2.x*ea.w;
                    float d3 = v2.y*ea.y + v2.z*ea.z + v2.w*ea.w;
                    red_add_v4(base + 128 + c0,
                               av[0]*d0*INV_SQRT3, av[1]*d1*INV_SQRT3,
                               av[2]*d2*INV_SQRT3, av[3]*d3*INV_SQRT3);
                }
            }
        }
    }
}

// ---------------------------------------------------------------------------
// Kernel 3: node output. 8 nodes per block, 256 threads.
// ---------------------------------------------------------------------------
__global__ void __launch_bounds__(256) k_out(
    const float* __restrict__ W0,
    const float* __restrict__ W1o,
    float* __restrict__ out)
{
    __shared__ __align__(16) float m_sm[8 * 1024];
    const int n0 = blockIdx.x * 8;
    const int t  = threadIdx.x;
    const int tc = t & 127;
    const int nb = (t >> 7) * 4;      // node group base: 0 or 4

    {
        const float4* src = (const float4*)(g_msg + n0 * 1024);
        float4* dst = (float4*)m_sm;
#pragma unroll
        for (int i = 0; i < 8; ++i) dst[t + 256 * i] = src[t + 256 * i];
    }
    __syncthreads();

    float a0[4], v0[4], v1[4], v2[4];
#pragma unroll
    for (int nn = 0; nn < 4; ++nn) { a0[nn]=0.f; v0[nn]=0.f; v1[nn]=0.f; v2[nn]=0.f; }

    for (int u = 0; u < 256; u += 4) {
        float w0[4], w1[4];
#pragma unroll
        for (int i = 0; i < 4; ++i) {
            w0[i] = W0 [(u + i) * 128 + tc];
            w1[i] = W1o[(u + i) * 128 + tc];
        }
#pragma unroll
        for (int nn = 0; nn < 4; ++nn) {
            const float* row = m_sm + (nb + nn) * 1024;
            float4 ms = *(const float4*)&row[u];
            a0[nn] += ms.x * w0[0] + ms.y * w0[1] + ms.z * w0[2] + ms.w * w0[3];
            float4 va = *(const float4*)&row[256 + u * 3];
            float4 vb = *(const float4*)&row[256 + u * 3 + 4];
            float4 vc = *(const float4*)&row[256 + u * 3 + 8];
            v0[nn] += va.x * w1[0] + va.w * w1[1] + vb.z * w1[2] + vc.y * w1[3];
            v1[nn] += va.y * w1[0] + vb.x * w1[1] + vb.w * w1[2] + vc.z * w1[3];
            v2[nn] += va.z * w1[0] + vb.y * w1[1] + vc.x * w1[2] + vc.w * w1[3];
        }
    }

#pragma unroll
    for (int nn = 0; nn < 4; ++nn) {
        *(float4*)(out + (n0 + nb + nn) * 512 + tc * 4) =
            make_float4(a0[nn] * OUT_SCALE, v0[nn] * OUT_SCALE,
                        v1[nn] * OUT_SCALE, v2[nn] * OUT_SCALE);
    }
}

// ---------------------------------------------------------------------------
// Launch
// ---------------------------------------------------------------------------
extern "C" void kernel_launch(void* const* d_in, const int* in_sizes, int n_in,
                              void* d_out, int out_size)
{
    const float* node_feats = (const float*)d_in[0];
    const float* edge_attrs = (const float*)d_in[1];
    const float* edge_feats = (const float*)d_in[2];
    const float* lengths    = (const float*)d_in[3];
    const int*   edge_index = (const int*)  d_in[4];
    const float* W_scalar   = (const float*)d_in[5];
    const float* W_up0      = (const float*)d_in[6];
    const float* W_up1      = (const float*)d_in[7];
    const float* W_mlp1     = (const float*)d_in[8];
    const float* b_mlp1     = (const float*)d_in[9];
    const float* W_mlp2     = (const float*)d_in[10];
    const float* b_mlp2     = (const float*)d_in[11];
    const float* W_mlp3     = (const float*)d_in[12];
    const float* W_out0     = (const float*)d_in[13];
    const float* W_out1     = (const float*)d_in[14];
    float* out = (float*)d_out;

    // Zero the message accumulator via async memset (graph-capturable,
    // no allocation) instead of a dedicated kernel.
    void* msg_ptr = nullptr;
    cudaGetSymbolAddress(&msg_ptr, g_msg);
    cudaMemsetAsync(msg_ptr, 0, (size_t)N_NODES * 1024 * sizeof(float), 0);

    k_w<<<dim3(128, 2), 128>>>(W_scalar, W_mlp1);
    k_node<<<N_NODES / 4, 128>>>(node_feats, W_up0, W_up1);
    k_edge<<<N_EDGES / TE, 128>>>(edge_attrs, edge_feats, lengths, edge_index,
                                  W_mlp1, b_mlp1, W_mlp2, b_mlp2, W_mlp3);
    k_out<<<N_NODES / 8, 256>>>(W_out0, W_out1, out);
}

// round 16
// speedup vs baseline: 1.1865x; 1.0154x over previous
#include <cuda_runtime.h>

#define N_NODES 10000
#define N_EDGES 160000
#define TE 32                    // edges per block in the edge kernel

#define INV_SQRT_MUL 0.08838834764831845f   // 1/sqrt(128)
#define INV_SQRT3    0.57735026918962576f
#define OUT_SCALE    0.00390625f            // (1/sqrt(256)) / 16

typedef unsigned long long ull;

// ---------------------------------------------------------------------------
// Scratch (device globals: allocation-free)
// ---------------------------------------------------------------------------
__device__ float g_hps[N_NODES * 128];   // s_in @ (inv * W_scalar @ W1[0:128])
__device__ float g_hpr[N_NODES * 128];   // s_in @ (inv * W_scalar @ W1[128:256])
__device__ float g_su [N_NODES * 128];   // s_up
__device__ float g_vup[N_NODES * 384];   // v_up, layout [n][w][i] (i fastest)
__device__ float g_msg[N_NODES * 1024];  // segment-sum accumulator
__device__ float g_Wsa[128 * 128];       // inv * W_scalar @ W1[0:128]
__device__ float g_Wsb[128 * 128];       // inv * W_scalar @ W1[128:256]

static __device__ __forceinline__ float silu(float x) {
    return x / (1.0f + __expf(-x));
}

static __device__ __forceinline__ void red_add_v4(float* addr, float a, float b,
                                                  float c, float d) {
    asm volatile("red.global.add.v4.f32 [%0], {%1, %2, %3, %4};"
                 :: "l"(addr), "f"(a), "f"(b), "f"(c), "f"(d) : "memory");
}

// ---- packed f32x2 helpers --------------------------------------------------
static __device__ __forceinline__ ull dup2(float x) {
    ull r; asm("mov.b64 %0, {%1, %1};" : "=l"(r) : "f"(x)); return r;
}
static __device__ __forceinline__ void fma2(ull& acc, ull a, ull b) {
    asm("fma.rn.f32x2 %0, %1, %2, %0;" : "+l"(acc) : "l"(a), "l"(b));
}
static __device__ __forceinline__ float2 unpack2(ull p) {
    float2 f; asm("mov.b64 {%0, %1}, %2;" : "=f"(f.x), "=f"(f.y) : "l"(p)); return f;
}

// ---------------------------------------------------------------------------
// Kernel W: fold W_scalar into the first MLP layer.
// ---------------------------------------------------------------------------
__global__ void __launch_bounds__(128) k_w(
    const float* __restrict__ Ws, const float* __restrict__ W1)
{
    __shared__ float row[128];
    const int u = blockIdx.x, t = threadIdx.x;
    row[t] = Ws[u * 128 + t];
    __syncthreads();
    const float* W1p = W1 + (blockIdx.y ? 128 * 128 : 0);
    float a = 0.f;
#pragma unroll 4
    for (int c = 0; c < 128; ++c) a += row[c] * W1p[c * 128 + t];
    (blockIdx.y ? g_Wsb : g_Wsa)[u * 128 + t] = a * INV_SQRT_MUL;
}

// ---------------------------------------------------------------------------
// Kernel 1: per-node precompute, 4 nodes per block (round-9 version).
// ---------------------------------------------------------------------------
__global__ void __launch_bounds__(128) k_node(
    const float* __restrict__ nf,
    const float* __restrict__ Wu0,
    const float* __restrict__ Wu1)
{
    __shared__ float s_sh[4][128];
    __shared__ float v_sh[4][384];
    const int n0 = blockIdx.x * 4;
    const int t = threadIdx.x;

#pragma unroll
    for (int nn = 0; nn < 4; ++nn) {
        const float* src = nf + (n0 + nn) * 512;
        s_sh[nn][t]       = src[t];
        v_sh[nn][t]       = src[128 + t];
        v_sh[nn][t + 128] = src[256 + t];
        v_sh[nn][t + 256] = src[384 + t];
    }
    __syncthreads();

    float as[4], ar[4], a1[4], av0[4], av1[4], av2[4];
#pragma unroll
    for (int nn = 0; nn < 4; ++nn) {
        as[nn]=0.f; ar[nn]=0.f; a1[nn]=0.f; av0[nn]=0.f; av1[nn]=0.f; av2[nn]=0.f;
    }

#pragma unroll 2
    for (int u = 0; u < 128; ++u) {
        float wsa = g_Wsa[u * 128 + t];
        float wsb = g_Wsb[u * 128 + t];
        float wu0 = Wu0[u * 128 + t];
        float wu1 = Wu1[u * 128 + t];
#pragma unroll
        for (int nn = 0; nn < 4; ++nn) {
            float s = s_sh[nn][u];
            as[nn] += s * wsa;
            ar[nn] += s * wsb;
            a1[nn] += s * wu0;
            av0[nn] += v_sh[nn][u * 3 + 0] * wu1;
            av1[nn] += v_sh[nn][u * 3 + 1] * wu1;
            av2[nn] += v_sh[nn][u * 3 + 2] * wu1;
        }
    }
#pragma unroll
    for (int nn = 0; nn < 4; ++nn) {
        int n = n0 + nn;
        g_hps[n * 128 + t] = as[nn];
        g_hpr[n * 128 + t] = ar[nn];
        g_su [n * 128 + t] = a1[nn] * INV_SQRT_MUL;
        g_vup[n * 384 + t * 3 + 0] = av0[nn] * INV_SQRT_MUL;
        g_vup[n * 384 + t * 3 + 1] = av1[nn] * INV_SQRT_MUL;
        g_vup[n * 384 + t * 3 + 2] = av2[nn] * INV_SQRT_MUL;
    }
}

// ---------------------------------------------------------------------------
// Kernel 2: per-edge MLP + message + scatter, f32x2 edge-pair packing.
// (Round-9 version, verbatim: proven 797-803us.)
// ---------------------------------------------------------------------------
__global__ void __launch_bounds__(128, 8) k_edge(
    const float* __restrict__ edge_attrs,
    const float* __restrict__ edge_feats,
    const float* __restrict__ lengths,
    const int*   __restrict__ edge_index,
    const float* __restrict__ W1, const float* __restrict__ b1,
    const float* __restrict__ W2, const float* __restrict__ b2,
    const float* __restrict__ W3)
{
    __shared__ __align__(16) float2 hT[128][18];   // [col k][edge pair], 144B rows
    __shared__ int s_idx[2][TE];                   // [0]=snd, [1]=rcv

    const int t  = threadIdx.x;
    const int cg = t & 31;
    const int c0 = cg * 4;
    const int wp = t >> 5;
    const int e0 = wp * 8;
    const int p0 = wp * 4;
    const int ebase = blockIdx.x * TE;

    if (t < 64) {
        const int e = t & 31;
        const int r = t >> 5;
        s_idx[r][e] = edge_index[r * N_EDGES + ebase + e];
    }
    __syncthreads();

    // ---- layer 1 (folded): per pair, compute both edges' 4 cols ----
    {
        float4 bb = *(const float4*)(b1 + c0);
#pragma unroll
        for (int jp = 0; jp < 4; ++jp) {
            float a2[2][4];
#pragma unroll
            for (int h = 0; h < 2; ++h) {
                const int el  = e0 + 2 * jp + h;
                const int eg  = ebase + el;
                const int snd = s_idx[0][el];
                const int rcv = s_idx[1][el];
                float4 hs = *(const float4*)(g_hps + snd * 128 + c0);
                float4 hr = *(const float4*)(g_hpr + rcv * 128 + c0);
                float a[4] = { bb.x + hs.x + hr.x, bb.y + hs.y + hr.y,
                               bb.z + hs.z + hr.z, bb.w + hs.w + hr.w };
                float ef[9];
                {
                    float4 q0 = *(const float4*)(edge_feats + eg * 8);
                    float4 q1 = *(const float4*)(edge_feats + eg * 8 + 4);
                    ef[0]=q0.x; ef[1]=q0.y; ef[2]=q0.z; ef[3]=q0.w;
                    ef[4]=q1.x; ef[5]=q1.y; ef[6]=q1.z; ef[7]=q1.w;
                    ef[8]=lengths[eg];
                }
#pragma unroll
                for (int r = 0; r < 9; ++r) {
                    float4 w = *(const float4*)(W1 + (256 + r) * 128 + c0);
                    a[0] += ef[r] * w.x; a[1] += ef[r] * w.y;
                    a[2] += ef[r] * w.z; a[3] += ef[r] * w.w;
                }
                a2[h][0]=silu(a[0]); a2[h][1]=silu(a[1]);
                a2[h][2]=silu(a[2]); a2[h][3]=silu(a[3]);
            }
#pragma unroll
            for (int i = 0; i < 4; ++i)
                hT[c0 + i][p0 + jp] = make_float2(a2[0][i], a2[1][i]);
        }
    }
    __syncthreads();

    // ---- layer 2: 128 -> 128, silu; acc[col][pair] ----
    {
        ull acc[4][4];
        {
            float4 b = *(const float4*)(b2 + c0);
            ull b0 = dup2(b.x), b1d = dup2(b.y), b2d = dup2(b.z), b3 = dup2(b.w);
#pragma unroll
            for (int jp = 0; jp < 4; ++jp) {
                acc[0][jp] = b0; acc[1][jp] = b1d; acc[2][jp] = b2d; acc[3][jp] = b3;
            }
        }
#pragma unroll 2
        for (int k = 0; k < 128; ++k) {
            float4 w = *(const float4*)(W2 + k * 128 + c0);
            ull wd0 = dup2(w.x), wd1 = dup2(w.y), wd2 = dup2(w.z), wd3 = dup2(w.w);
            ulonglong2 xa = *(const ulonglong2*)&hT[k][p0];
            ulonglong2 xb = *(const ulonglong2*)&hT[k][p0 + 2];
            fma2(acc[0][0], wd0, xa.x); fma2(acc[0][1], wd0, xa.y);
            fma2(acc[0][2], wd0, xb.x); fma2(acc[0][3], wd0, xb.y);
            fma2(acc[1][0], wd1, xa.x); fma2(acc[1][1], wd1, xa.y);
            fma2(acc[1][2], wd1, xb.x); fma2(acc[1][3], wd1, xb.y);
            fma2(acc[2][0], wd2, xa.x); fma2(acc[2][1], wd2, xa.y);
            fma2(acc[2][2], wd2, xb.x); fma2(acc[2][3], wd2, xb.y);
            fma2(acc[3][0], wd3, xa.x); fma2(acc[3][1], wd3, xa.y);
            fma2(acc[3][2], wd3, xb.x); fma2(acc[3][3], wd3, xb.y);
        }
        __syncthreads();             // all h1 reads complete
#pragma unroll
        for (int i = 0; i < 4; ++i)
#pragma unroll
            for (int jp = 0; jp < 4; ++jp) {
                float2 v = unpack2(acc[i][jp]);
                hT[c0 + i][p0 + jp] = make_float2(silu(v.x), silu(v.y));
            }
    }
    __syncthreads();
    // h2 now lives in hT, read-only below.

    // ======== layer 3: four single-segment sweeps, fused scatter ==========
#pragma unroll 1
    for (int seg = 0; seg < 4; ++seg) {
        ull acc[4][4];
#pragma unroll
        for (int i = 0; i < 4; ++i)
#pragma unroll
            for (int jp = 0; jp < 4; ++jp) acc[i][jp] = 0;

        const float* Wseg = W3 + seg * 128 + c0;
#pragma unroll 2
        for (int k = 0; k < 128; ++k) {
            float4 w = *(const float4*)(Wseg + k * 512);
            ull wd0 = dup2(w.x), wd1 = dup2(w.y), wd2 = dup2(w.z), wd3 = dup2(w.w);
            ulonglong2 xa = *(const ulonglong2*)&hT[k][p0];
            ulonglong2 xb = *(const ulonglong2*)&hT[k][p0 + 2];
            fma2(acc[0][0], wd0, xa.x); fma2(acc[0][1], wd0, xa.y);
            fma2(acc[0][2], wd0, xb.x); fma2(acc[0][3], wd0, xb.y);
            fma2(acc[1][0], wd1, xa.x); fma2(acc[1][1], wd1, xa.y);
            fma2(acc[1][2], wd1, xb.x); fma2(acc[1][3], wd1, xb.y);
            fma2(acc[2][0], wd2, xa.x); fma2(acc[2][1], wd2, xa.y);
            fma2(acc[2][2], wd2, xb.x); fma2(acc[2][3], wd2, xb.y);
            fma2(acc[3][0], wd3, xa.x); fma2(acc[3][1], wd3, xa.y);
            fma2(acc[3][2], wd3, xb.x); fma2(acc[3][3], wd3, xb.y);
        }

        // ---- fused scatter for this segment ----
#pragma unroll
        for (int jp = 0; jp < 4; ++jp) {
            float2 vc0 = unpack2(acc[0][jp]);
            float2 vc1 = unpack2(acc[1][jp]);
            float2 vc2 = unpack2(acc[2][jp]);
            float2 vc3 = unpack2(acc[3][jp]);
#pragma unroll
            for (int h = 0; h < 2; ++h) {
                const int el  = e0 + 2 * jp + h;
                const int eg  = ebase + el;
                const int snd = s_idx[0][el];
                const int rcv = s_idx[1][el];
                float4 ea = *(const float4*)(edge_attrs + eg * 4);
                const float av[4] = { h ? vc0.y : vc0.x, h ? vc1.y : vc1.x,
                                      h ? vc2.y : vc2.x, h ? vc3.y : vc3.x };
                float* base = g_msg + rcv * 1024;

                if (seg == 0) {          // m0a = w0*se*y0 -> [0,128)
                    float4 sev = *(const float4*)(g_su + snd * 128 + c0);
                    red_add_v4(base + c0,
                               av[0]*sev.x*ea.x, av[1]*sev.y*ea.x,
                               av[2]*sev.z*ea.x, av[3]*sev.w*ea.x);
                } else if (seg == 1) {   // m1a = (w1*se) (x) y1 -> [256,640)
                    float4 sev = *(const float4*)(g_su + snd * 128 + c0);
                    const float se[4] = {sev.x, sev.y, sev.z, sev.w};
                    float o[12];
#pragma unroll
                    for (int m = 0; m < 4; ++m) {
                        float t1 = av[m] * se[m];
                        o[3*m+0] = t1 * ea.y; o[3*m+1] = t1 * ea.z; o[3*m+2] = t1 * ea.w;
                    }
                    float* p = base + 256 + c0 * 3;
                    red_add_v4(p,     o[0], o[1], o[2],  o[3]);
                    red_add_v4(p + 4, o[4], o[5], o[6],  o[7]);
                    red_add_v4(p + 8, o[8], o[9], o[10], o[11]);
                } else if (seg == 2) {   // m1b = (w2*y0) * ve -> [640,1024)
                    const float4* pv = (const float4*)(g_vup + snd * 384 + c0 * 3);
                    float4 v0 = pv[0], v1 = pv[1], v2 = pv[2];
                    float o[12];
                    o[0]  = av[0]*ea.x*v0.x; o[1]  = av[0]*ea.x*v0.y; o[2]  = av[0]*ea.x*v0.z;
                    o[3]  = av[1]*ea.x*v0.w; o[4]  = av[1]*ea.x*v1.x; o[5]  = av[1]*ea.x*v1.y;
                    o[6]  = av[2]*ea.x*v1.z; o[7]  = av[2]*ea.x*v1.w; o[8]  = av[2]*ea.x*v2.x;
                    o[9]  = av[3]*ea.x*v2.y; o[10] = av[3]*ea.x*v2.z; o[11] = av[3]*ea.x*v2.w;
                    float* p = base + 640 + c0 * 3;
                    red_add_v4(p,     o[0], o[1], o[2],  o[3]);
                    red_add_v4(p + 4, o[4], o[5], o[6],  o[7]);
                    red_add_v4(p + 8, o[8], o[9], o[10], o[11]);
                } else {                 // m0b = w3*(ve.y1)*inv_sqrt3 -> [128,256)
                    const float4* pv = (const float4*)(g_vup + snd * 384 + c0 * 3);
                    float4 v0 = pv[0], v1 = pv[1], v2 = pv[2];
                    float d0 = v0.x*ea.y + v0.y*ea.z + v0.z*ea.w;
                    float d1 = v0.w*ea.y + v1.x*ea.z + v1.y*ea.w;
                    float d2 = v1.z*ea.y + v1.w*ea.z + v2.x*ea.w;
                    float d3 = v2.y*ea.y + v2.z*ea.z + v2.w*ea.w;
                    red_add_v4(base + 128 + c0,
                               av[0]*d0*INV_SQRT3, av[1]*d1*INV_SQRT3,
                               av[2]*d2*INV_SQRT3, av[3]*d3*INV_SQRT3);
                }
            }
        }
    }
}

// ---------------------------------------------------------------------------
// Kernel 3: node output. 8 nodes per block, 128 threads, thread t = column.
// Every weight load amortized over 8 nodes; single clean u-loop.
// ---------------------------------------------------------------------------
__global__ void __launch_bounds__(128) k_out(
    const float* __restrict__ W0,
    const float* __restrict__ W1o,
    float* __restrict__ out)
{
    __shared__ __align__(16) float m_sm[8][1024];
    const int n0 = blockIdx.x * 8;
    const int t  = threadIdx.x;

#pragma unroll
    for (int nn = 0; nn < 8; ++nn) {
        const float4* src = (const float4*)(g_msg + (n0 + nn) * 1024);
        ((float4*)m_sm[nn])[t]       = src[t];
        ((float4*)m_sm[nn])[t + 128] = src[t + 128];
    }
    __syncthreads();

    float a0[8], v0[8], v1[8], v2[8];
#pragma unroll
    for (int nn = 0; nn < 8; ++nn) { a0[nn]=0.f; v0[nn]=0.f; v1[nn]=0.f; v2[nn]=0.f; }

    for (int u = 0; u < 256; u += 4) {
        float w0[4], w1[4];
#pragma unroll
        for (int i = 0; i < 4; ++i) {
            w0[i] = W0 [(u + i) * 128 + t];
            w1[i] = W1o[(u + i) * 128 + t];
        }
#pragma unroll
        for (int nn = 0; nn < 8; ++nn) {
            const float* row = m_sm[nn];
            float4 ms = *(const float4*)&row[u];
            a0[nn] += ms.x * w0[0] + ms.y * w0[1] + ms.z * w0[2] + ms.w * w0[3];
            float4 va = *(const float4*)&row[256 + u * 3];
            float4 vb = *(const float4*)&row[256 + u * 3 + 4];
            float4 vc = *(const float4*)&row[256 + u * 3 + 8];
            // u+0: (va.x va.y va.z)  u+1: (va.w vb.x vb.y)
            // u+2: (vb.z vb.w vc.x)  u+3: (vc.y vc.z vc.w)
            v0[nn] += va.x * w1[0] + va.w * w1[1] + vb.z * w1[2] + vc.y * w1[3];
            v1[nn] += va.y * w1[0] + vb.x * w1[1] + vb.w * w1[2] + vc.z * w1[3];
            v2[nn] += va.z * w1[0] + vb.y * w1[1] + vc.x * w1[2] + vc.w * w1[3];
        }
    }

#pragma unroll
    for (int nn = 0; nn < 8; ++nn) {
        *(float4*)(out + (n0 + nn) * 512 + t * 4) =
            make_float4(a0[nn] * OUT_SCALE, v0[nn] * OUT_SCALE,
                        v1[nn] * OUT_SCALE, v2[nn] * OUT_SCALE);
    }
}

// ---------------------------------------------------------------------------
// Launch
// ---------------------------------------------------------------------------
extern "C" void kernel_launch(void* const* d_in, const int* in_sizes, int n_in,
                              void* d_out, int out_size)
{
    const float* node_feats = (const float*)d_in[0];
    const float* edge_attrs = (const float*)d_in[1];
    const float* edge_feats = (const float*)d_in[2];
    const float* lengths    = (const float*)d_in[3];
    const int*   edge_index = (const int*)  d_in[4];
    const float* W_scalar   = (const float*)d_in[5];
    const float* W_up0      = (const float*)d_in[6];
    const float* W_up1      = (const float*)d_in[7];
    const float* W_mlp1     = (const float*)d_in[8];
    const float* b_mlp1     = (const float*)d_in[9];
    const float* W_mlp2     = (const float*)d_in[10];
    const float* b_mlp2     = (const float*)d_in[11];
    const float* W_mlp3     = (const float*)d_in[12];
    const float* W_out0     = (const float*)d_in[13];
    const float* W_out1     = (const float*)d_in[14];
    float* out = (float*)d_out;

    // Zero the message accumulator via async memset (graph-capturable,
    // no allocation).
    void* msg_ptr = nullptr;
    cudaGetSymbolAddress(&msg_ptr, g_msg);
    cudaMemsetAsync(msg_ptr, 0, (size_t)N_NODES * 1024 * sizeof(float), 0);

    k_w<<<dim3(128, 2), 128>>>(W_scalar, W_mlp1);
    k_node<<<N_NODES / 4, 128>>>(node_feats, W_up0, W_up1);
    k_edge<<<N_EDGES / TE, 128>>>(edge_attrs, edge_feats, lengths, edge_index,
                                  W_mlp1, b_mlp1, W_mlp2, b_mlp2, W_mlp3);
    k_out<<<N_NODES / 8, 128>>>(W_out0, W_out1, out);
}